// round 2
// baseline (speedup 1.0000x reference)
#include <cuda_runtime.h>
#include <math.h>

// Problem constants (fixed shapes)
#define E      768
#define H      12
#define NW     8
#define DK     64
#define KFEAT  16            // 8 cos + 8 sin features
#define KROWS  17            // + bias row
#define PN     (KROWS * E)   // 13056 folded-weight elements

#define TOK_PER_BLK 64
#define MAIN_THREADS 128
#define RCHUNKS 16
#define RCHUNK  (E / RCHUNKS)   // 48

// Scratch (device globals: allocation-free rule)
__device__ __align__(16) float g_P[PN];                 // pre-fold matrix  [17][768] over (h*64+d)
__device__ __align__(16) float g_R[PN];                 // folded weights   [17][768] over e
__device__ __align__(16) float g_part[RCHUNKS * PN];    // deterministic partial sums

// ---------------------------------------------------------------------------
// packed fp32x2 helpers (FFMA2: PTX-only, sm_100+)
// ---------------------------------------------------------------------------
__device__ __forceinline__ unsigned long long fma2(unsigned long long a,
                                                   unsigned long long b,
                                                   unsigned long long c) {
    unsigned long long d;
    asm("fma.rn.f32x2 %0, %1, %2, %3;" : "=l"(d) : "l"(a), "l"(b), "l"(c));
    return d;
}
__device__ __forceinline__ unsigned long long pack2(float v) {
    unsigned long long d;
    asm("mov.b64 %0, {%1, %1};" : "=l"(d) : "f"(v));
    return d;
}
__device__ __forceinline__ void stcs64(void* p, unsigned long long v) {
    asm volatile("st.global.cs.b64 [%0], %1;" :: "l"(p), "l"(v) : "memory");
}

// ---------------------------------------------------------------------------
// Kernel A: build P[k][r], r = h*64+d
//   k in [0,8):   cos(theta[h][w=k])   * W_proj[h][w][d]
//   k in [8,16): -sin(theta[h][w=k-8]) * W_proj[h][w][d]
//   k == 16:      b_proj[h][d]
// ---------------------------------------------------------------------------
__global__ void build_P_kernel(const float* __restrict__ theta,
                               const float* __restrict__ W_proj,
                               const float* __restrict__ b_proj) {
    int i = blockIdx.x * blockDim.x + threadIdx.x;
    if (i >= PN) return;
    int k = i / E;
    int r = i - k * E;          // h*64 + d
    int h = r >> 6;
    int d = r & 63;
    float v;
    if (k < 8) {
        int w = k;
        v = cosf(theta[h * NW + w]) * W_proj[(h * NW + w) * DK + d];
    } else if (k < 16) {
        int w = k - 8;
        v = -sinf(theta[h * NW + w]) * W_proj[(h * NW + w) * DK + d];
    } else {
        v = b_proj[r];
    }
    g_P[i] = v;
}

// ---------------------------------------------------------------------------
// Kernel B: partial R = P @ W_out over r-chunks (deterministic partial slabs)
//   grid (6 e-chunks of 128, 16 r-chunks of 48), 128 threads
// ---------------------------------------------------------------------------
__global__ void fold_R_partial_kernel(const float* __restrict__ W_out) {
    __shared__ float Ps[KROWS][RCHUNK];
    const int e  = blockIdx.x * 128 + threadIdx.x;
    const int r0 = blockIdx.y * RCHUNK;

    for (int idx = threadIdx.x; idx < KROWS * RCHUNK; idx += 128) {
        int k  = idx / RCHUNK;
        int rr = idx - k * RCHUNK;
        Ps[k][rr] = g_P[k * E + r0 + rr];
    }
    __syncthreads();

    float acc[KROWS];
#pragma unroll
    for (int k = 0; k < KROWS; k++) acc[k] = 0.f;

#pragma unroll 8
    for (int rr = 0; rr < RCHUNK; rr++) {
        float wo = __ldg(&W_out[(size_t)(r0 + rr) * E + e]);
#pragma unroll
        for (int k = 0; k < KROWS; k++) acc[k] = fmaf(Ps[k][rr], wo, acc[k]);
    }

    float* dst = g_part + (size_t)blockIdx.y * PN;
#pragma unroll
    for (int k = 0; k < KROWS; k++) dst[k * E + e] = acc[k];
}

// ---------------------------------------------------------------------------
// Kernel C: reduce partials (+ b_out into bias row)
// ---------------------------------------------------------------------------
__global__ void reduce_R_kernel(const float* __restrict__ b_out) {
    int i = blockIdx.x * blockDim.x + threadIdx.x;
    if (i >= PN) return;
    float s = 0.f;
#pragma unroll
    for (int j = 0; j < RCHUNKS; j++) s += g_part[(size_t)j * PN + i];
    if (i >= 16 * E) s += b_out[i - 16 * E];
    g_R[i] = s;
}

// ---------------------------------------------------------------------------
// Main kernel: per token 8 sincos, then [ntok,16] @ R[16,768] + bias
//   128 threads; each thread owns 3 column-pairs (packed f32x2 weights in regs)
// ---------------------------------------------------------------------------
__global__ void qattn_main_kernel(const float* __restrict__ x,
                                  float* __restrict__ out) {
    __shared__ float s_cs[TOK_PER_BLK][KFEAT];   // [tok][0..7]=cos, [8..15]=sin

    const int tid  = threadIdx.x;
    const long tok0 = (long)blockIdx.x * TOK_PER_BLK;

    // ---- Phase 1: sincos of x[:, :8] for this token tile ----
    {
        int t    = tid >> 1;         // 0..63
        int half = tid & 1;          // 0..1
        const float4 xv = *(const float4*)(x + (size_t)(tok0 + t) * E + half * 4);
        float s, c;
        int w0 = half * 4;
        sincosf(xv.x, &s, &c); s_cs[t][w0 + 0] = c; s_cs[t][8 + w0 + 0] = s;
        sincosf(xv.y, &s, &c); s_cs[t][w0 + 1] = c; s_cs[t][8 + w0 + 1] = s;
        sincosf(xv.z, &s, &c); s_cs[t][w0 + 2] = c; s_cs[t][8 + w0 + 2] = s;
        sincosf(xv.w, &s, &c); s_cs[t][w0 + 3] = c; s_cs[t][8 + w0 + 3] = s;
    }

    // ---- Phase 2: load 3 column-pairs of folded weights into registers ----
    const int c0 = 2 * tid;          // columns (c0, c0+1)
    const int c1 = c0 + 256;
    const int c2 = c0 + 512;
    unsigned long long w0[KROWS], w1[KROWS], w2[KROWS];
#pragma unroll
    for (int k = 0; k < KROWS; k++) {
        w0[k] = *(const unsigned long long*)(g_R + k * E + c0);
        w1[k] = *(const unsigned long long*)(g_R + k * E + c1);
        w2[k] = *(const unsigned long long*)(g_R + k * E + c2);
    }

    __syncthreads();

    // ---- Token loop ----
#pragma unroll 1
    for (int t = 0; t < TOK_PER_BLK; t++) {
        float cs[KFEAT];
        *(float4*)&cs[0]  = *(const float4*)&s_cs[t][0];
        *(float4*)&cs[4]  = *(const float4*)&s_cs[t][4];
        *(float4*)&cs[8]  = *(const float4*)&s_cs[t][8];
        *(float4*)&cs[12] = *(const float4*)&s_cs[t][12];

        unsigned long long a0 = w0[16];   // bias pairs
        unsigned long long a1 = w1[16];
        unsigned long long a2 = w2[16];
#pragma unroll
        for (int k = 0; k < KFEAT; k++) {
            unsigned long long a = pack2(cs[k]);
            a0 = fma2(a, w0[k], a0);
            a1 = fma2(a, w1[k], a1);
            a2 = fma2(a, w2[k], a2);
        }

        float* orow = out + (size_t)(tok0 + t) * E;
        stcs64(orow + c0, a0);
        stcs64(orow + c1, a1);
        stcs64(orow + c2, a2);
    }
}

// ---------------------------------------------------------------------------
// Launch
// inputs (metadata order): x[B,S,E] f32, theta[H,NW] f32, W_proj[H,NW,DK] f32,
//                          b_proj[H,DK] f32, W_out[E,E] f32, b_out[E] f32
// output: [B,S,E] f32
// ---------------------------------------------------------------------------
extern "C" void kernel_launch(void* const* d_in, const int* in_sizes, int n_in,
                              void* d_out, int out_size) {
    const float* x      = (const float*)d_in[0];
    const float* theta  = (const float*)d_in[1];
    const float* W_proj = (const float*)d_in[2];
    const float* b_proj = (const float*)d_in[3];
    const float* W_out  = (const float*)d_in[4];
    const float* b_out  = (const float*)d_in[5];
    float* out = (float*)d_out;

    const int ntok = in_sizes[0] / E;               // B*S = 32768

    // Prologue: fold weights (must be recomputed every call — deterministic)
    build_P_kernel<<<(PN + 255) / 256, 256>>>(theta, W_proj, b_proj);
    fold_R_partial_kernel<<<dim3(E / 128, RCHUNKS), 128>>>(W_out);
    reduce_R_kernel<<<(PN + 255) / 256, 256>>>(b_out);

    // Main pass
    qattn_main_kernel<<<ntok / TOK_PER_BLK, MAIN_THREADS>>>(x, out);

    (void)n_in; (void)out_size;
}